// round 16
// baseline (speedup 1.0000x reference)
#include <cuda_runtime.h>

// RITS recurrence v15: warp-specialized producer/consumer split.
//  128 CTAs x 256 thr, 2 samples/CTA, T=512 on-chip.
//  ON  (warps 0-3): critical path  x_hat -> z_hat -> c_hat/cc -> cc@Wcc -> gates.
//      Wcc (W_lstm rows 0-63) register-resident (64 ull).
//  OFF (warps 4-7): hdec@U (U regs, 64 ull), and one step AHEAD: gamma_h,
//      gamma_x, beta-pre, m@Wm (Wm = W_lstm rows 64-127, smem float4 slab).
//  Named barriers: 1 = ON internal (128), 4 = OFF internal (128),
//  2 = zU/zM rendezvous (OFF arrive, ON sync, 256), 3 = h publish (256).
//  bp/zM/gh double-buffered by t-parity; inputs triple-buffered.

#define TT 512
#define NIMP (256L * 3 * 512 * 64)
typedef unsigned long long ull;
typedef ulonglong2 ull2;

#define FMA2(acc, a, b) \
    asm("fma.rn.f32x2 %0, %1, %2, %0;" : "+l"(acc) : "l"(a), "l"(b))
#define BAR_SYNC(id, cnt)   asm volatile("bar.sync %0, %1;"   :: "r"(id), "r"(cnt) : "memory")
#define BAR_ARRIVE(id, cnt) asm volatile("bar.arrive %0, %1;" :: "r"(id), "r"(cnt) : "memory")

__device__ __forceinline__ ull pk2(float x, float y) {
    ull r; asm("mov.b64 %0, {%1, %2};" : "=l"(r) : "f"(x), "f"(y)); return r;
}
__device__ __forceinline__ float fsum(ull v) {
    float2 r; asm("mov.b64 {%0, %1}, %2;" : "=f"(r.x), "=f"(r.y) : "l"(v));
    return r.x + r.y;
}
__device__ __forceinline__ float sigf(float x) { return 1.f / (1.f + __expf(-x)); }

__global__ __launch_bounds__(256, 1) void rits_kernel(
    const float* __restrict__ inputs,
    const float* __restrict__ W_hist, const float* __restrict__ b_hist,
    const float* __restrict__ W_feat, const float* __restrict__ b_feat,
    const float* __restrict__ W_gx,   const float* __restrict__ b_gx,
    const float* __restrict__ W_gh,   const float* __restrict__ b_gh,
    const float* __restrict__ W_beta, const float* __restrict__ b_beta,
    const float* __restrict__ W_lstm, const float* __restrict__ U_lstm,
    const float* __restrict__ b_lstm,
    const float* __restrict__ W_out,  const float* __restrict__ b_out,
    float* __restrict__ out)
{
    extern __shared__ __align__(16) float sm[];
    float* sWh2   = sm;              // 4096  W_hist pairs {w[2q][j],w[2q+1][j]}
    float* sWgh2  = sWh2   + 4096;   // 4096  W_gh pairs
    float* sWf2   = sWgh2  + 4096;   // 4096  W_feat_c pairs
    float* sWb2   = sWf2   + 4096;   // 8192  W_beta pairs
    float* slabWm = sWb2   + 8192;   // 16384 W_lstm rows 64-127, per-thread f4 slab
    float* sWgx   = slabWm + 16384;  // 64
    float* sbh    = sWgx + 64;
    float* sbf    = sbh  + 64;
    float* sbgx   = sbf  + 64;
    float* sbb    = sbgx + 64;
    float* sbgh   = sbb  + 64;
    float* sbl    = sbgh + 64;       // 256
    float* hS     = sbl  + 256;      // 128  [s*64+j]
    float* xcS    = hS   + 128;      // 128
    float* ccS    = xcS  + 128;      // 128
    float* hdecS  = ccS  + 128;      // 128
    float* gxS    = hdecS+ 128;      // 128
    float* ghS    = gxS  + 128;      // 256  double-buffered [buf*128 + s*64+j]
    float* bpS    = ghS  + 256;      // 256  double-buffered
    float* zUS    = bpS  + 256;      // 512  [s*256 + col]
    float* zMS    = zUS  + 512;      // 1024 double-buffered [buf*512 + s*256+col]
    float* inb    = zMS  + 1024;     // 3*384 triple-buffered [c*128 + s*64 + j]
    // total = 41,344 floats = 165,376 bytes

    const int tid  = threadIdx.x;
    const int bid  = blockIdx.x;
    const int u    = tid & 127;

    // ---- pack pair-layout weights ----
    for (int i = tid; i < 2048; i += 256) {
        int q = i >> 6, j = i & 63;
        *(float2*)&sWh2[i * 2]  = make_float2(W_hist[(2*q)*64 + j], W_hist[(2*q+1)*64 + j]);
        *(float2*)&sWgh2[i * 2] = make_float2(W_gh[(2*q)*64 + j],   W_gh[(2*q+1)*64 + j]);
    }
    for (int i = tid; i < 2048; i += 256) {
        int q = i >> 6, j = i & 63;
        float a = (2*q     == j) ? 0.f : W_feat[(2*q)*64 + j];
        float b = (2*q + 1 == j) ? 0.f : W_feat[(2*q+1)*64 + j];
        *(float2*)&sWf2[i * 2] = make_float2(a, b);
    }
    for (int i = tid; i < 4096; i += 256) {
        int q = i >> 6, j = i & 63;
        *(float2*)&sWb2[i * 2] = make_float2(W_beta[(2*q)*64 + j], W_beta[(2*q+1)*64 + j]);
    }
    // ---- Wm slab: float4 at [(cb*16+it)*128 + uu] = W_lstm rows 64+4it.. of col
    for (int idx = tid; idx < 4096; idx += 256) {
        int cb = idx >> 11, rem = idx & 2047, it = rem >> 7, uu = rem & 127;
        int col = (uu & 1) * 64 + (uu >> 1) + cb * 128;
        int row = 64 + 4 * it;
        ((float4*)slabWm)[idx] = make_float4(
            W_lstm[row*256 + col],     W_lstm[(row+1)*256 + col],
            W_lstm[(row+2)*256 + col], W_lstm[(row+3)*256 + col]);
    }
    if (tid < 64) {
        sWgx[tid] = W_gx[tid * 64 + tid];
        sbh[tid]  = b_hist[tid];
        sbf[tid]  = b_feat[tid];
        sbgx[tid] = b_gx[tid];
        sbb[tid]  = b_beta[tid];
        sbgh[tid] = b_gh[tid];
    }
    sbl[tid] = b_lstm[tid];
    if (tid < 128) hS[tid] = 0.f;

    // ---- initial input load: t=0 -> buf0, t=1 -> buf1 (float4) ----
    if (tid < 192) {
        int tb = tid / 96, r = tid % 96;
        int c = r / 32, rr = r % 32, s = rr / 16, qq = rr % 16;
        long src = (((long)(2 * bid + s) * 3 + c) * TT + tb) * 64 + 4 * qq;
        *(float4*)&inb[tb * 384 + c * 128 + s * 64 + 4 * qq] =
            *(const float4*)&inputs[src];
    }
    __syncthreads();

    // ---- PROLOGUE (all threads duplicate; identical writes are benign) ----
    {
        int s0 = u & 1, j0 = u >> 1;
        float d0 = inb[256 + s0 * 64 + j0];
        gxS[s0 * 64 + j0] = __expf(-fmaxf(d0 * sWgx[j0] + sbgx[j0], 0.f));
    }
    __syncthreads();
    {
        int s0 = u & 1, j0 = u >> 1;
        // ghS[0]: d(0)@W_gh
        ull a0 = 0, a1 = 0;
#pragma unroll
        for (int i = 0; i < 16; i++) {
            ull2 av = *(const ull2*)&inb[256 + s0 * 64 + 4 * i];
            ull wa = *(const ull*)&sWgh2[((2*i)*64 + j0) * 2];
            ull wb = *(const ull*)&sWgh2[((2*i+1)*64 + j0) * 2];
            FMA2(a0, wa, av.x); FMA2(a1, wb, av.y);
        }
        ghS[s0 * 64 + j0] = __expf(-fmaxf(fsum(a0) + fsum(a1) + sbgh[j0], 0.f));
        // bpS[0]: [gx(0); m(0)]@W_beta
        ull b0 = 0, b1 = 0;
#pragma unroll
        for (int i = 0; i < 16; i++) {
            ull2 av = *(const ull2*)&gxS[s0 * 64 + 4 * i];
            ull wa = *(const ull*)&sWb2[((2*i)*64 + j0) * 2];
            ull wb = *(const ull*)&sWb2[((2*i+1)*64 + j0) * 2];
            FMA2(b0, wa, av.x); FMA2(b1, wb, av.y);
        }
#pragma unroll
        for (int i = 0; i < 16; i++) {
            ull2 av = *(const ull2*)&inb[128 + s0 * 64 + 4 * i];
            ull wa = *(const ull*)&sWb2[((32 + 2*i)*64 + j0) * 2];
            ull wb = *(const ull*)&sWb2[((33 + 2*i)*64 + j0) * 2];
            FMA2(b0, wa, av.x); FMA2(b1, wb, av.y);
        }
        bpS[s0 * 64 + j0] = fsum(b0) + fsum(b1) + sbb[j0];
        // zMS[0]: m(0)@Wm slab  (cols colA/colB of thread u)
        ull mA0 = 0, mA1 = 0, mB0 = 0, mB1 = 0;
#pragma unroll
        for (int it = 0; it < 16; it++) {
            ull2 wA = *(const ull2*)&slabWm[((0*16 + it)*128 + u) * 4];
            ull2 wB = *(const ull2*)&slabWm[((1*16 + it)*128 + u) * 4];
            ull2 m0 = *(const ull2*)&inb[128 + 4 * it];
            ull2 m1 = *(const ull2*)&inb[128 + 64 + 4 * it];
            FMA2(mA0, wA.x, m0.x); FMA2(mA0, wA.y, m0.y);
            FMA2(mA1, wA.x, m1.x); FMA2(mA1, wA.y, m1.y);
            FMA2(mB0, wB.x, m0.x); FMA2(mB0, wB.y, m0.y);
            FMA2(mB1, wB.x, m1.x); FMA2(mB1, wB.y, m1.y);
        }
        int colA = (u & 1) * 64 + (u >> 1), colB = colA + 128;
        zMS[colA]       = fsum(mA0);
        zMS[256 + colA] = fsum(mA1);
        zMS[colB]       = fsum(mB0);
        zMS[256 + colB] = fsum(mB1);
    }
    __syncthreads();

    // ============================ MAIN LOOP ============================
    if (tid < 128) {
        // ------------------------- ON-PATH -------------------------
        const int q = u & 1, j = u >> 1;          // A/B sample = q; C gate-pair = q
        const int colA = q * 64 + j, colB = colA + 128;
        ull WA[32], WB[32];
#pragma unroll
        for (int p = 0; p < 32; p++) {
            WA[p] = pk2(W_lstm[(2*p)*256 + colA], W_lstm[(2*p+1)*256 + colA]);
            WB[p] = pk2(W_lstm[(2*p)*256 + colB], W_lstm[(2*p+1)*256 + colB]);
        }
        const float blA = sbl[colA], blB = sbl[colB];
        float cReg = 0.f;
        float* outx = out + (((long)(2*bid + q) * 3 + 0) * TT) * 64 + j;
        float* outz = out + (((long)(2*bid + q) * 3 + 1) * TT) * 64 + j;
        float* outc = out + (((long)(2*bid + q) * 3 + 2) * TT) * 64 + j;

        int bc = 0;
        for (int t = 0; t < TT; t++) {
            const float* bufc = inb + bc * 384;
            const int cur = t & 1;
            // A: x_hat = h[q]@W_hist col j
            ull a0 = 0, a1 = 0;
#pragma unroll
            for (int i = 0; i < 16; i++) {
                ull2 hv = *(const ull2*)&hS[q * 64 + 4 * i];
                ull wa = *(const ull*)&sWh2[((2*i)*64 + j) * 2];
                ull wb = *(const ull*)&sWh2[((2*i+1)*64 + j) * 2];
                FMA2(a0, wa, hv.x); FMA2(a1, wb, hv.y);
            }
            float xh = fsum(a0) + fsum(a1) + sbh[j];
            float x = bufc[q * 64 + j], m = bufc[128 + q * 64 + j];
            xcS[q * 64 + j] = m * x + (1.f - m) * xh;
            outx[(long)t * 64] = xh;
            BAR_SYNC(1, 128);
            // B: z_hat = xc[q]@W_feat_c col j
            ull z0 = 0, z1 = 0;
#pragma unroll
            for (int i = 0; i < 16; i++) {
                ull2 av = *(const ull2*)&xcS[q * 64 + 4 * i];
                ull wa = *(const ull*)&sWf2[((2*i)*64 + j) * 2];
                ull wb = *(const ull*)&sWf2[((2*i+1)*64 + j) * 2];
                FMA2(z0, wa, av.x); FMA2(z1, wb, av.y);
            }
            float zh = fsum(z0) + fsum(z1) + sbf[j];
            float be = sigf(bpS[cur * 128 + q * 64 + j]);
            float ch = be * zh + (1.f - be) * xh;
            float cc = m * x + (1.f - m) * ch;
            ccS[q * 64 + j] = cc;
            outz[(long)t * 64] = zh;
            outc[(long)t * 64] = ch;
            BAR_SYNC(1, 128);
            // C: zcc = cc@Wcc (rows 0-63), both samples, 2 cols
            ull cA0 = 0, cA1 = 0, cB0 = 0, cB1 = 0;
#pragma unroll
            for (int i = 0; i < 16; i++) {
                ull2 c0 = *(const ull2*)&ccS[4 * i];
                ull2 c1 = *(const ull2*)&ccS[64 + 4 * i];
                FMA2(cA0, WA[2*i], c0.x); FMA2(cA0, WA[2*i+1], c0.y);
                FMA2(cA1, WA[2*i], c1.x); FMA2(cA1, WA[2*i+1], c1.y);
                FMA2(cB0, WB[2*i], c0.x); FMA2(cB0, WB[2*i+1], c0.y);
                FMA2(cB1, WB[2*i], c1.x); FMA2(cB1, WB[2*i+1], c1.y);
            }
            BAR_SYNC(2, 256);    // zU(t) ready (zM(t)/bp(t) from prev step)
            float zAs0 = fsum(cA0) + zUS[colA]       + zMS[cur*512 + colA]       + blA;
            float zAs1 = fsum(cA1) + zUS[256 + colA] + zMS[cur*512 + 256 + colA] + blA;
            float zBs0 = fsum(cB0) + zUS[colB]       + zMS[cur*512 + colB]       + blB;
            float zBs1 = fsum(cB1) + zUS[256 + colB] + zMS[cur*512 + 256 + colB] + blB;
            // exchange with gate partner (lane^1): send other-sample values
            float sA = q ? zAs0 : zAs1;
            float sB = q ? zBs0 : zBs1;
            float rA = __shfl_xor_sync(0xffffffffu, sA, 1);
            float rB = __shfl_xor_sync(0xffffffffu, sB, 1);
            float zAm = q ? zAs1 : zAs0;
            float zBm = q ? zBs1 : zBs0;
            float iv = q ? rA : zAm;
            float fv = q ? zAm : rA;
            float gv = q ? rB : zBm;
            float ov = q ? zBm : rB;
            float cn = sigf(fv) * cReg + sigf(iv) * tanhf(gv);
            cReg = cn;
            hS[q * 64 + j] = sigf(ov) * tanhf(cn);
            BAR_SYNC(3, 256);    // publish h(t)
            if (++bc == 3) bc = 0;
        }
    } else {
        // ------------------------- OFF-PATH -------------------------
        const int q = u & 1, j = u >> 1;
        const int colA = q * 64 + j, colB = colA + 128;
        ull UA[32], UB[32];
#pragma unroll
        for (int p = 0; p < 32; p++) {
            UA[p] = pk2(U_lstm[(2*p)*256 + colA], U_lstm[(2*p+1)*256 + colA]);
            UB[p] = pk2(U_lstm[(2*p)*256 + colB], U_lstm[(2*p+1)*256 + colB]);
        }
        // prefetch mapping (u < 96)
        const int pc = u / 32, prr = u % 32, ps = prr / 16, pq = prr % 16;
        const long pbase = ((long)(2 * bid + ps) * 3 + pc) * TT * 64 + 4 * pq;
        const int poff = pc * 128 + ps * 64 + 4 * pq;

        int bc = 0;
        for (int t = 0; t < TT; t++) {
            const float* bufn = inb + ((bc + 1) % 3) * 384;   // inputs(t+1)
            const int cur = t & 1, nxt = cur ^ 1;
            const bool hasN = (t + 1 < TT);
            // pointwise: hdec(t), gamma_x(t+1)
            hdecS[q * 64 + j] = hS[q * 64 + j] * ghS[cur * 128 + q * 64 + j];
            if (hasN) {
                float dn = bufn[256 + q * 64 + j];
                gxS[q * 64 + j] = __expf(-fmaxf(dn * sWgx[j] + sbgx[j], 0.f));
            }
            BAR_SYNC(4, 128);
            // zU(t) = hdec@U (regs), both samples, 2 cols
            {
                ull uA0 = 0, uA1 = 0, uB0 = 0, uB1 = 0;
#pragma unroll
                for (int i = 0; i < 16; i++) {
                    ull2 h0 = *(const ull2*)&hdecS[4 * i];
                    ull2 h1 = *(const ull2*)&hdecS[64 + 4 * i];
                    FMA2(uA0, UA[2*i], h0.x); FMA2(uA0, UA[2*i+1], h0.y);
                    FMA2(uA1, UA[2*i], h1.x); FMA2(uA1, UA[2*i+1], h1.y);
                    FMA2(uB0, UB[2*i], h0.x); FMA2(uB0, UB[2*i+1], h0.y);
                    FMA2(uB1, UB[2*i], h1.x); FMA2(uB1, UB[2*i+1], h1.y);
                }
                zUS[colA]       = fsum(uA0);
                zUS[256 + colA] = fsum(uA1);
                zUS[colB]       = fsum(uB0);
                zUS[256 + colB] = fsum(uB1);
            }
            BAR_ARRIVE(2, 256);
            if (hasN) {
                // gamma_h(t+1): d(t+1)@W_gh
                ull g0 = 0, g1 = 0;
#pragma unroll
                for (int i = 0; i < 16; i++) {
                    ull2 av = *(const ull2*)&bufn[256 + q * 64 + 4 * i];
                    ull wa = *(const ull*)&sWgh2[((2*i)*64 + j) * 2];
                    ull wb = *(const ull*)&sWgh2[((2*i+1)*64 + j) * 2];
                    FMA2(g0, wa, av.x); FMA2(g1, wb, av.y);
                }
                ghS[nxt * 128 + q * 64 + j] =
                    __expf(-fmaxf(fsum(g0) + fsum(g1) + sbgh[j], 0.f));
                // beta-pre(t+1): [gx(t+1); m(t+1)]@W_beta
                ull b0 = 0, b1 = 0;
#pragma unroll
                for (int i = 0; i < 16; i++) {
                    ull2 av = *(const ull2*)&gxS[q * 64 + 4 * i];
                    ull wa = *(const ull*)&sWb2[((2*i)*64 + j) * 2];
                    ull wb = *(const ull*)&sWb2[((2*i+1)*64 + j) * 2];
                    FMA2(b0, wa, av.x); FMA2(b1, wb, av.y);
                }
#pragma unroll
                for (int i = 0; i < 16; i++) {
                    ull2 av = *(const ull2*)&bufn[128 + q * 64 + 4 * i];
                    ull wa = *(const ull*)&sWb2[((32 + 2*i)*64 + j) * 2];
                    ull wb = *(const ull*)&sWb2[((33 + 2*i)*64 + j) * 2];
                    FMA2(b0, wa, av.x); FMA2(b1, wb, av.y);
                }
                bpS[nxt * 128 + q * 64 + j] = fsum(b0) + fsum(b1) + sbb[j];
                // zM(t+1) = m(t+1)@Wm slab
                ull mA0 = 0, mA1 = 0, mB0 = 0, mB1 = 0;
#pragma unroll
                for (int it = 0; it < 16; it++) {
                    ull2 wA = *(const ull2*)&slabWm[((0*16 + it)*128 + u) * 4];
                    ull2 wB = *(const ull2*)&slabWm[((1*16 + it)*128 + u) * 4];
                    ull2 m0 = *(const ull2*)&bufn[128 + 4 * it];
                    ull2 m1 = *(const ull2*)&bufn[128 + 64 + 4 * it];
                    FMA2(mA0, wA.x, m0.x); FMA2(mA0, wA.y, m0.y);
                    FMA2(mA1, wA.x, m1.x); FMA2(mA1, wA.y, m1.y);
                    FMA2(mB0, wB.x, m0.x); FMA2(mB0, wB.y, m0.y);
                    FMA2(mB1, wB.x, m1.x); FMA2(mB1, wB.y, m1.y);
                }
                zMS[nxt*512 + colA]       = fsum(mA0);
                zMS[nxt*512 + 256 + colA] = fsum(mA1);
                zMS[nxt*512 + colB]       = fsum(mB0);
                zMS[nxt*512 + 256 + colB] = fsum(mB1);
            }
            // prefetch inputs(t+2) into buffer (bc+2)%3
            if (u < 96 && t + 2 < TT) {
                float4 v = *(const float4*)&inputs[pbase + (long)(t + 2) * 64];
                *(float4*)&inb[((bc + 2) % 3) * 384 + poff] = v;
            }
            BAR_SYNC(3, 256);
            if (++bc == 3) bc = 0;
        }
    }
    __syncthreads();

    // ===== predictions: sigmoid(h_last @ W_out + b_out) =====
    if (tid < 64) {
        int s = tid >> 5, l = tid & 31;
        float v = hS[s * 64 + l] * W_out[l] + hS[s * 64 + 32 + l] * W_out[32 + l];
#pragma unroll
        for (int off = 16; off; off >>= 1)
            v += __shfl_down_sync(0xffffffffu, v, off);
        if (l == 0)
            out[NIMP + 2 * bid + s] = 1.f / (1.f + __expf(-(v + b_out[0])));
    }
}

extern "C" void kernel_launch(void* const* d_in, const int* in_sizes, int n_in,
                              void* d_out, int out_size)
{
    const float* inputs = (const float*)d_in[0];
    const float* W_hist = (const float*)d_in[1];
    const float* b_hist = (const float*)d_in[2];
    const float* W_feat = (const float*)d_in[3];
    const float* b_feat = (const float*)d_in[4];
    const float* W_gx   = (const float*)d_in[5];
    const float* b_gx   = (const float*)d_in[6];
    const float* W_gh   = (const float*)d_in[7];
    const float* b_gh   = (const float*)d_in[8];
    const float* W_beta = (const float*)d_in[9];
    const float* b_beta = (const float*)d_in[10];
    const float* W_lstm = (const float*)d_in[11];
    const float* U_lstm = (const float*)d_in[12];
    const float* b_lstm = (const float*)d_in[13];
    const float* W_out  = (const float*)d_in[14];
    const float* b_out  = (const float*)d_in[15];

    const int smem_bytes = 41344 * (int)sizeof(float);   // 165,376 B
    cudaFuncSetAttribute(rits_kernel,
                         cudaFuncAttributeMaxDynamicSharedMemorySize, smem_bytes);

    rits_kernel<<<128, 256, smem_bytes>>>(
        inputs, W_hist, b_hist, W_feat, b_feat, W_gx, b_gx, W_gh, b_gh,
        W_beta, b_beta, W_lstm, U_lstm, b_lstm, W_out, b_out,
        (float*)d_out);
}

// round 17
// speedup vs baseline: 1.1414x; 1.1414x over previous
#include <cuda_runtime.h>
#include <cuda_bf16.h>

// RITS recurrence v16 = round-3 v2 champion (1066.8us), byte-identical except:
//   tanhf (slow precise software routine, 2x serial on the C2 critical path)
//   replaced by fast sigma-identity tanh via MUFU: ~7 instr, |err| < 1e-6.

#define TT 512
#define NIMP (256L * 3 * 512 * 64)
typedef unsigned long long ull;

#define FMA2(acc, a, b) \
    asm("fma.rn.f32x2 %0, %1, %2, %0;" : "+l"(acc) : "l"(a), "l"(b))

__device__ __forceinline__ ull pk2(float x, float y) {
    ull r; asm("mov.b64 %0, {%1, %2};" : "=l"(r) : "f"(x), "f"(y)); return r;
}
__device__ __forceinline__ float2 upk(ull v) {
    float2 r; asm("mov.b64 {%0, %1}, %2;" : "=f"(r.x), "=f"(r.y) : "l"(v)); return r;
}
__device__ __forceinline__ float ftanh(float x) {
    float e = __expf(-2.f * fabsf(x));
    float t = __fdividef(1.f - e, 1.f + e);
    return copysignf(t, x);
}

__global__ __launch_bounds__(256, 1) void rits_kernel(
    const float* __restrict__ inputs,
    const float* __restrict__ W_hist, const float* __restrict__ b_hist,
    const float* __restrict__ W_feat, const float* __restrict__ b_feat,
    const float* __restrict__ W_gx,   const float* __restrict__ b_gx,
    const float* __restrict__ W_gh,   const float* __restrict__ b_gh,
    const float* __restrict__ W_beta, const float* __restrict__ b_beta,
    const float* __restrict__ W_lstm, const float* __restrict__ U_lstm,
    const float* __restrict__ b_lstm,
    const float* __restrict__ W_out,  const float* __restrict__ b_out,
    float* __restrict__ out)
{
    extern __shared__ __align__(16) float sm[];
    float* sWh2  = sm;             // 4096  W_hist pairs {w[2q][j],w[2q+1][j]}
    float* sWf2  = sWh2  + 4096;   // 4096  W_feat (diag zeroed) pairs
    float* sWb2  = sWf2  + 4096;   // 8192  W_beta pairs
    float* sWgh2 = sWb2  + 8192;   // 4096  W_gh pairs
    float* sWgx  = sWgh2 + 4096;   // 64    diag(W_gx)
    float* sbh   = sWgx + 64;
    float* sbf   = sbh  + 64;
    float* sbgx  = sbf  + 64;
    float* sbb   = sbgx + 64;
    float* sbgh  = sbb  + 64;
    float* sbl   = sbgh + 64;      // 256
    float* hS    = sbl  + 256;     // 128  h[s][j]
    float* cS    = hS   + 128;     // 128
    float* hdec  = cS   + 128;     // 128
    float* xhat  = hdec + 128;     // 128
    float* xc    = xhat + 128;     // 128
    float* gx    = xc   + 128;     // 128
    float* ccm   = gx   + 128;     // 256  [s][cc(64)|m(64)]
    float* zbuf  = ccm  + 256;     // 512  [s][o]
    float* pA    = zbuf + 512;     // 512
    float* pz    = pA   + 512;     // 256
    float* pb    = pz   + 256;     // 512
    float* inb   = pb   + 512;     // 2*384 double-buffered [c][s][k]

    const int tid = threadIdx.x;
    const int bid = blockIdx.x;

    // ---- pack smem weights: {W[2q][j], W[2q+1][j]} at float offset (q*64+j)*2
    for (int i = tid; i < 2048; i += 256) {
        int q = i >> 6, j = i & 63;
        *(float2*)&sWh2[i * 2]  = make_float2(W_hist[(2*q)*64 + j], W_hist[(2*q+1)*64 + j]);
        *(float2*)&sWgh2[i * 2] = make_float2(W_gh[(2*q)*64 + j],   W_gh[(2*q+1)*64 + j]);
    }
    for (int i = tid; i < 2048; i += 256) {
        int q = i >> 6, j = i & 63;
        float a = (2*q     == j) ? 0.f : W_feat[(2*q)*64 + j];
        float b = (2*q + 1 == j) ? 0.f : W_feat[(2*q+1)*64 + j];
        *(float2*)&sWf2[i * 2] = make_float2(a, b);
    }
    for (int i = tid; i < 4096; i += 256) {
        int q = i >> 6, j = i & 63;
        *(float2*)&sWb2[i * 2] = make_float2(W_beta[(2*q)*64 + j], W_beta[(2*q+1)*64 + j]);
    }
    if (tid < 64) {
        sWgx[tid] = W_gx[tid * 64 + tid];
        sbh[tid]  = b_hist[tid];
        sbf[tid]  = b_feat[tid];
        sbgx[tid] = b_gx[tid];
        sbb[tid]  = b_beta[tid];
        sbgh[tid] = b_gh[tid];
    }
    sbl[tid] = b_lstm[tid];
    if (tid < 128) { hS[tid] = 0.f; cS[tid] = 0.f; }

    // ---- register-stationary weights: column `tid`, packed over k pairs ----
    ull wl2[64], ul2[32];
#pragma unroll
    for (int q = 0; q < 64; q++)
        wl2[q] = pk2(W_lstm[(2*q)*256 + tid], W_lstm[(2*q+1)*256 + tid]);
#pragma unroll
    for (int q = 0; q < 32; q++)
        ul2[q] = pk2(U_lstm[(2*q)*256 + tid], U_lstm[(2*q+1)*256 + tid]);

    // ---- input loader mapping (threads 0..191) ----
    const int ls = tid / 96;            // sample
    const int lr = tid % 96;
    const int lc = lr / 32;             // channel 0=x 1=m 2=d
    const int ll = lr % 32;
    const long lbase = ((long)(2 * bid + ls) * 3 + lc) * TT * 64;

    if (tid < 192) {
        float2 v = *(const float2*)&inputs[lbase + 2 * ll];
        *(float2*)&inb[lc * 128 + ls * 64 + 2 * ll] = v;
    }
    __syncthreads();

    const int g  = tid >> 7;            // phase A half
    const int kh = (tid >> 6) & 1;      // phase A k-half
    const int jA = tid & 63;
    const int u  = tid >> 6;            // phase B quarter
    const int jB = tid & 63;

    int p = 0;
    for (int t = 0; t < TT; t++) {
        float* bufc = inb + p * 384;

        float2 pf = make_float2(0.f, 0.f);
        if (tid < 192 && t + 1 < TT)
            pf = *(const float2*)&inputs[lbase + (long)(t + 1) * 64 + 2 * ll];

        // ===== Phase A: x_hat pre (h@W_hist) / gamma_h pre (d@W_gh) =====
        {
            const float* act = g ? (bufc + 256) : hS;
            const float* W   = g ? sWgh2 : sWh2;
            ull acc0 = 0, acc1 = 0;
#pragma unroll
            for (int i = 0; i < 8; i++) {
                int k = kh * 32 + 4 * i, q = k >> 1;
                ulonglong2 a0 = *(const ulonglong2*)&act[k];
                ulonglong2 a1 = *(const ulonglong2*)&act[64 + k];
                ull wa = *(const ull*)&W[(q * 64 + jA) * 2];
                ull wb = *(const ull*)&W[((q + 1) * 64 + jA) * 2];
                FMA2(acc0, wa, a0.x); FMA2(acc0, wb, a0.y);
                FMA2(acc1, wa, a1.x); FMA2(acc1, wb, a1.y);
            }
            float2 r0 = upk(acc0), r1 = upk(acc1);
            pA[(g * 2 + kh) * 128 + jA]      = r0.x + r0.y;
            pA[(g * 2 + kh) * 128 + 64 + jA] = r1.x + r1.y;
        }
        __syncthreads();

        // ===== Phase A2: x_hat, x_c, gamma_x | gamma_h, h_dec =====
        {
            int r = tid & 127, s = r >> 6, j = r & 63;
            if (g == 0) {
                float v = pA[s * 64 + j] + pA[128 + s * 64 + j] + sbh[j];
                xhat[r] = v;
                float x = bufc[r], m = bufc[128 + r], d = bufc[256 + r];
                xc[r] = m * x + (1.f - m) * v;
                gx[r] = __expf(-fmaxf(d * sWgx[j] + sbgx[j], 0.f));
                long n = 2 * bid + s;
                out[((n * 3 + 0) * (long)TT + t) * 64 + j] = v;
            } else {
                float v = pA[256 + s * 64 + j] + pA[384 + s * 64 + j];
                float gh = __expf(-fmaxf(v + sbgh[j], 0.f));
                hdec[r] = hS[r] * gh;
            }
        }
        __syncthreads();

        // ===== Phase B: z_hat (xc@W_feat_c) + beta pre ([gx;m]@W_beta) =====
        {
            ull z0 = 0, z1 = 0, b0 = 0, b1 = 0;
            if (u < 2) {
#pragma unroll
                for (int i = 0; i < 8; i++) {            // z_hat, 32 k
                    int k = u * 32 + 4 * i, q = k >> 1;
                    ulonglong2 a0 = *(const ulonglong2*)&xc[k];
                    ulonglong2 a1 = *(const ulonglong2*)&xc[64 + k];
                    ull wa = *(const ull*)&sWf2[(q * 64 + jB) * 2];
                    ull wb = *(const ull*)&sWf2[((q + 1) * 64 + jB) * 2];
                    FMA2(z0, wa, a0.x); FMA2(z0, wb, a0.y);
                    FMA2(z1, wa, a1.x); FMA2(z1, wb, a1.y);
                }
#pragma unroll
                for (int i = 0; i < 4; i++) {            // beta, 16 k (gamma_x)
                    int k = u * 16 + 4 * i, q = k >> 1;
                    ulonglong2 a0 = *(const ulonglong2*)&gx[k];
                    ulonglong2 a1 = *(const ulonglong2*)&gx[64 + k];
                    ull wa = *(const ull*)&sWb2[(q * 64 + jB) * 2];
                    ull wb = *(const ull*)&sWb2[((q + 1) * 64 + jB) * 2];
                    FMA2(b0, wa, a0.x); FMA2(b0, wb, a0.y);
                    FMA2(b1, wa, a1.x); FMA2(b1, wb, a1.y);
                }
                float2 r0 = upk(z0), r1 = upk(z1);
                pz[u * 128 + jB]      = r0.x + r0.y;
                pz[u * 128 + 64 + jB] = r1.x + r1.y;
            } else if (u == 2) {
#pragma unroll
                for (int i = 0; i < 8; i++) {            // beta, k 32..63 (gamma_x)
                    int k = 32 + 4 * i, q = k >> 1;
                    ulonglong2 a0 = *(const ulonglong2*)&gx[k];
                    ulonglong2 a1 = *(const ulonglong2*)&gx[64 + k];
                    ull wa = *(const ull*)&sWb2[(q * 64 + jB) * 2];
                    ull wb = *(const ull*)&sWb2[((q + 1) * 64 + jB) * 2];
                    FMA2(b0, wa, a0.x); FMA2(b0, wb, a0.y);
                    FMA2(b1, wa, a1.x); FMA2(b1, wb, a1.y);
                }
#pragma unroll
                for (int i = 0; i < 4; i++) {            // beta, k 64..79 (m)
                    int k = 64 + 4 * i, q = k >> 1;
                    ulonglong2 a0 = *(const ulonglong2*)&bufc[128 + (k - 64)];
                    ulonglong2 a1 = *(const ulonglong2*)&bufc[128 + 64 + (k - 64)];
                    ull wa = *(const ull*)&sWb2[(q * 64 + jB) * 2];
                    ull wb = *(const ull*)&sWb2[((q + 1) * 64 + jB) * 2];
                    FMA2(b0, wa, a0.x); FMA2(b0, wb, a0.y);
                    FMA2(b1, wa, a1.x); FMA2(b1, wb, a1.y);
                }
            } else {
#pragma unroll
                for (int i = 0; i < 12; i++) {           // beta, k 80..127 (m)
                    int k = 80 + 4 * i, q = k >> 1;
                    ulonglong2 a0 = *(const ulonglong2*)&bufc[128 + (k - 64)];
                    ulonglong2 a1 = *(const ulonglong2*)&bufc[128 + 64 + (k - 64)];
                    ull wa = *(const ull*)&sWb2[(q * 64 + jB) * 2];
                    ull wb = *(const ull*)&sWb2[((q + 1) * 64 + jB) * 2];
                    FMA2(b0, wa, a0.x); FMA2(b0, wb, a0.y);
                    FMA2(b1, wa, a1.x); FMA2(b1, wb, a1.y);
                }
            }
            float2 r0 = upk(b0), r1 = upk(b1);
            pb[u * 128 + jB]      = r0.x + r0.y;
            pb[u * 128 + 64 + jB] = r1.x + r1.y;
        }
        __syncthreads();

        // ===== Phase B2: beta, c_hat, c_c =====
        if (tid < 128) {
            int s = tid >> 6, j = tid & 63, r = tid;
            float zh   = pz[r] + pz[128 + r] + sbf[j];
            float bpre = pb[r] + pb[128 + r] + pb[256 + r] + pb[384 + r] + sbb[j];
            float beta = 1.f / (1.f + __expf(-bpre));
            float xh   = xhat[r];
            float chat = beta * zh + (1.f - beta) * xh;
            float x = bufc[r], m = bufc[128 + r];
            ccm[s * 128 + j]      = m * x + (1.f - m) * chat;
            ccm[s * 128 + 64 + j] = m;
            long n = 2 * bid + s;
            out[((n * 3 + 1) * (long)TT + t) * 64 + j] = zh;
            out[((n * 3 + 2) * (long)TT + t) * 64 + j] = chat;
        }
        __syncthreads();

        // ===== Phase C: z[o] = [c_c;m]@W_lstm (regs) + h_dec@U (regs) + b =====
        {
            ull acc0 = 0, acc1 = 0;
#pragma unroll
            for (int i = 0; i < 32; i++) {
                ulonglong2 a0 = *(const ulonglong2*)&ccm[4 * i];
                ulonglong2 a1 = *(const ulonglong2*)&ccm[128 + 4 * i];
                FMA2(acc0, wl2[2*i], a0.x); FMA2(acc0, wl2[2*i+1], a0.y);
                FMA2(acc1, wl2[2*i], a1.x); FMA2(acc1, wl2[2*i+1], a1.y);
            }
#pragma unroll
            for (int i = 0; i < 16; i++) {
                ulonglong2 a0 = *(const ulonglong2*)&hdec[4 * i];
                ulonglong2 a1 = *(const ulonglong2*)&hdec[64 + 4 * i];
                FMA2(acc0, ul2[2*i], a0.x); FMA2(acc0, ul2[2*i+1], a0.y);
                FMA2(acc1, ul2[2*i], a1.x); FMA2(acc1, ul2[2*i+1], a1.y);
            }
            float2 r0 = upk(acc0), r1 = upk(acc1);
            float b = sbl[tid];
            zbuf[tid]       = r0.x + r0.y + b;
            zbuf[256 + tid] = r1.x + r1.y + b;
        }
        __syncthreads();

        // ===== Phase C2: LSTM gates (fast tanh); commit prefetched inputs ====
        if (tid < 128) {
            int s = tid >> 6, j = tid & 63;
            const float* zs = zbuf + s * 256;
            float iv = zs[j], fv = zs[64 + j], gv = zs[128 + j], ov = zs[192 + j];
            float co = cS[tid];
            float si = 1.f / (1.f + __expf(-iv));
            float sf = 1.f / (1.f + __expf(-fv));
            float so = 1.f / (1.f + __expf(-ov));
            float cn = sf * co + si * ftanh(gv);
            cS[tid] = cn;
            hS[tid] = so * ftanh(cn);
        }
        if (tid < 192 && t + 1 < TT)
            *(float2*)&inb[(p ^ 1) * 384 + lc * 128 + ls * 64 + 2 * ll] = pf;
        p ^= 1;
        __syncthreads();
    }

    // ===== predictions: sigmoid(h_last @ W_out + b_out) =====
    if (tid < 64) {
        int s = tid >> 5, l = tid & 31;
        float v = hS[s * 64 + l] * W_out[l] + hS[s * 64 + 32 + l] * W_out[32 + l];
#pragma unroll
        for (int off = 16; off; off >>= 1)
            v += __shfl_down_sync(0xffffffffu, v, off);
        if (l == 0)
            out[NIMP + 2 * bid + s] = 1.f / (1.f + __expf(-(v + b_out[0])));
    }
}

extern "C" void kernel_launch(void* const* d_in, const int* in_sizes, int n_in,
                              void* d_out, int out_size)
{
    const float* inputs = (const float*)d_in[0];
    const float* W_hist = (const float*)d_in[1];
    const float* b_hist = (const float*)d_in[2];
    const float* W_feat = (const float*)d_in[3];
    const float* b_feat = (const float*)d_in[4];
    const float* W_gx   = (const float*)d_in[5];
    const float* b_gx   = (const float*)d_in[6];
    const float* W_gh   = (const float*)d_in[7];
    const float* b_gh   = (const float*)d_in[8];
    const float* W_beta = (const float*)d_in[9];
    const float* b_beta = (const float*)d_in[10];
    const float* W_lstm = (const float*)d_in[11];
    const float* U_lstm = (const float*)d_in[12];
    const float* b_lstm = (const float*)d_in[13];
    const float* W_out  = (const float*)d_in[14];
    const float* b_out  = (const float*)d_in[15];

    const int smem_bytes = 24704 * (int)sizeof(float);   // 98,816 B
    cudaFuncSetAttribute(rits_kernel,
                         cudaFuncAttributeMaxDynamicSharedMemorySize, smem_bytes);

    rits_kernel<<<128, 256, smem_bytes>>>(
        inputs, W_hist, b_hist, W_feat, b_feat, W_gx, b_gx, W_gh, b_gh,
        W_beta, b_beta, W_lstm, U_lstm, b_lstm, W_out, b_out,
        (float*)d_out);
}